// round 5
// baseline (speedup 1.0000x reference)
#include <cuda_runtime.h>
#include <math.h>

#define SEQ     16384
#define IN_DIM  512
#define HID     1024
#define OUT_DIM 256

#define NB      128     // scan blocks (<148 SMs => all co-resident)
#define SCAN_T  256

// ---- scratch (static __device__; no allocs anywhere) ----
__device__ float    g_xh[SEQ * HID];      // 64 MB  xh = input@Wxh.T + bias
__device__ float    g_outs[SEQ * HID];    // 64 MB  h_1..h_SEQ for GEMM3
__device__ float    g_hbuf[2][HID];       // double-buffered h (L2-hot)
__device__ unsigned g_flags[NB * 32];     // one flag per block, 128B apart
__device__ float    g_bias[HID];          // Wxh_b + Whh_b + bh

__device__ __forceinline__ void st_release_u32(unsigned* p, unsigned v) {
    asm volatile("st.release.gpu.global.u32 [%0], %1;" :: "l"(p), "r"(v) : "memory");
}
__device__ __forceinline__ unsigned ld_acquire_u32(const unsigned* p) {
    unsigned v;
    asm volatile("ld.acquire.gpu.global.u32 %0, [%1];" : "=r"(v) : "l"(p) : "memory");
    return v;
}

// ---------------------------------------------------------------- reset ----
__global__ void reset_kernel(const float* __restrict__ hidden,
                             const float* __restrict__ wxb,
                             const float* __restrict__ whb,
                             const float* __restrict__ bh) {
    int i = threadIdx.x;  // 1024 threads
    g_hbuf[0][i] = hidden[i];
    g_bias[i]    = wxb[i] + whb[i] + bh[i];
#pragma unroll
    for (int j = 0; j < 4; j++)                 // clear all 4096 flag words
        g_flags[i * 4 + j] = 0u;
}

// --------------------------------------------------- generic NT fp32 GEMM --
// C[m][n] = sum_k A[m][k] * B[n][k] + bias[n]
__global__ void gemm_nt_bias(const float* __restrict__ A,
                             const float* __restrict__ B,
                             const float* __restrict__ bias,
                             float* __restrict__ C,
                             int M, int N, int K) {
    __shared__ float As[16][65];
    __shared__ float Bs[16][65];
    const int tid = threadIdx.x;
    const int bx = blockIdx.x;
    const int by = blockIdx.y;
    const int tm = (tid >> 4) << 2;
    const int tn = (tid & 15) << 2;
    const int lr = tid >> 2;
    const int lk = (tid & 3) << 2;

    const float* Ap = A + (size_t)(by * 64 + lr) * K + lk;
    const float* Bp = B + (size_t)(bx * 64 + lr) * K + lk;

    float acc[4][4] = {};

    for (int k0 = 0; k0 < K; k0 += 16) {
        float4 av = *(const float4*)(Ap + k0);
        float4 bv = *(const float4*)(Bp + k0);
        As[lk + 0][lr] = av.x; As[lk + 1][lr] = av.y;
        As[lk + 2][lr] = av.z; As[lk + 3][lr] = av.w;
        Bs[lk + 0][lr] = bv.x; Bs[lk + 1][lr] = bv.y;
        Bs[lk + 2][lr] = bv.z; Bs[lk + 3][lr] = bv.w;
        __syncthreads();
#pragma unroll
        for (int k = 0; k < 16; k++) {
            float ra[4], rb[4];
#pragma unroll
            for (int i = 0; i < 4; i++) ra[i] = As[k][tm + i];
#pragma unroll
            for (int j = 0; j < 4; j++) rb[j] = Bs[k][tn + j];
#pragma unroll
            for (int i = 0; i < 4; i++)
#pragma unroll
                for (int j = 0; j < 4; j++)
                    acc[i][j] += ra[i] * rb[j];
        }
        __syncthreads();
    }

    float bb[4];
#pragma unroll
    for (int j = 0; j < 4; j++) bb[j] = bias[bx * 64 + tn + j];
#pragma unroll
    for (int i = 0; i < 4; i++) {
        int row = by * 64 + tm + i;
        float* cp = C + (size_t)row * N + bx * 64 + tn;
#pragma unroll
        for (int j = 0; j < 4; j++) cp[j] = acc[i][j] + bb[j];
    }
}

// ---------------------------------------------- flag-sync persistent scan --
// Block b owns rows b*8..b*8+7. Thread tid holds weights W[r][c0..c0+3] for
// all 8 rows (c0 = (tid>>1)*8 + (tid&1)*4) and gathers exactly the 16B its
// polled producer block wrote. No smem MV traffic, no atomics.
__global__ void __launch_bounds__(SCAN_T, 1)
scan_kernel(const float* __restrict__ Whh) {
    const int bid  = blockIdx.x;
    const int tid  = threadIdx.x;
    const int wid  = tid >> 5;
    const int lane = tid & 31;
    const int c0   = (tid >> 1) * 8 + (tid & 1) * 4;   // my 4 h-columns

    // weights: rows bid*8+r, columns c0..c0+3
    float4 w[8];
#pragma unroll
    for (int r = 0; r < 8; r++)
        w[r] = *(const float4*)&Whh[(size_t)(bid * 8 + r) * HID + c0];

    __shared__ float red[8][8];   // [warp][row]

    const unsigned* fp = &g_flags[(tid >> 1) * 32];    // producer block I watch

    // xh pipeline for threads 0..7 (row owners)
    const int myrow = bid * 8 + tid;                   // valid when tid < 8
    float xh_c = 0.f, xh_n = 0.f;
    if (tid < 8) {
        xh_c = g_xh[myrow];
        xh_n = g_xh[(size_t)HID + myrow];
    }

#pragma unroll 1
    for (int t = 0; t < SEQ; t++) {
        // wait for my producer block to publish step t, then gather its 16B
        if (t > 0)
            while (ld_acquire_u32(fp) < (unsigned)t) { }
        float4 hv = __ldcg((const float4*)&g_hbuf[t & 1][c0]);

        // partials for all 8 rows of this block
        float p[8];
#pragma unroll
        for (int r = 0; r < 8; r++)
            p[r] = fmaf(w[r].x, hv.x,
                   fmaf(w[r].y, hv.y,
                   fmaf(w[r].z, hv.z, w[r].w * hv.w)));

        // warp butterfly reduce (all lanes end with warp total)
#pragma unroll
        for (int off = 16; off > 0; off >>= 1)
#pragma unroll
            for (int r = 0; r < 8; r++)
                p[r] += __shfl_xor_sync(0xFFFFFFFFu, p[r], off);

        if (lane < 8) red[wid][lane] = p[lane];
        __syncthreads();

        if (tid < 8) {
            float s = red[0][tid] + red[1][tid] + red[2][tid] + red[3][tid]
                    + red[4][tid] + red[5][tid] + red[6][tid] + red[7][tid];
            float hn = tanhf(xh_c + s);
            __stcg(&g_hbuf[(t + 1) & 1][myrow], hn);
            g_outs[(size_t)t * HID + myrow] = hn;
            xh_c = xh_n;
            if (t + 2 < SEQ) xh_n = __ldg(&g_xh[(size_t)(t + 2) * HID + myrow]);
            __syncwarp(0x000000FFu);
            if (tid == 0)
                st_release_u32(&g_flags[bid * 32], (unsigned)(t + 1));
        }
        __syncthreads();   // red[][] consumed before next iteration rewrites it
    }
}

// ----------------------------------------------------------- row softmax ---
__global__ void softmax256(float* __restrict__ X) {
    const int r = blockIdx.x;
    const int tid = threadIdx.x;          // 256
    const int wid = tid >> 5, lane = tid & 31;
    __shared__ float red[8];

    float v = X[(size_t)r * OUT_DIM + tid];

    float m = v;
#pragma unroll
    for (int o = 16; o > 0; o >>= 1)
        m = fmaxf(m, __shfl_xor_sync(0xFFFFFFFFu, m, o));
    if (lane == 0) red[wid] = m;
    __syncthreads();
    if (tid == 0) {
        float mm = red[0];
#pragma unroll
        for (int i = 1; i < 8; i++) mm = fmaxf(mm, red[i]);
        red[0] = mm;
    }
    __syncthreads();
    const float bm = red[0];
    __syncthreads();

    float e = expf(v - bm);
    float s = e;
#pragma unroll
    for (int o = 16; o > 0; o >>= 1)
        s += __shfl_xor_sync(0xFFFFFFFFu, s, o);
    if (lane == 0) red[wid] = s;
    __syncthreads();
    if (tid == 0) {
        float ss = red[0];
#pragma unroll
        for (int i = 1; i < 8; i++) ss += red[i];
        red[0] = ss;
    }
    __syncthreads();
    X[(size_t)r * OUT_DIM + tid] = e / red[0];
}

// ------------------------------------------------------------------ launch -
extern "C" void kernel_launch(void* const* d_in, const int* in_sizes, int n_in,
                              void* d_out, int out_size) {
    const float* input  = (const float*)d_in[0];   // (SEQ, IN)
    const float* hidden = (const float*)d_in[1];   // (HID,)
    const float* Wxh_w  = (const float*)d_in[2];   // (HID, IN)
    const float* Wxh_b  = (const float*)d_in[3];   // (HID,)
    const float* Whh_w  = (const float*)d_in[4];   // (HID, HID)
    const float* Whh_b  = (const float*)d_in[5];   // (HID,)
    const float* bh     = (const float*)d_in[6];   // (HID,)
    const float* fc_w   = (const float*)d_in[7];   // (OUT, HID)
    const float* fc_b   = (const float*)d_in[8];   // (OUT,)
    float* out = (float*)d_out;                    // (SEQ, OUT)

    float* xh_ptr   = nullptr;
    float* outs_ptr = nullptr;
    float* bias_ptr = nullptr;
    cudaGetSymbolAddress((void**)&xh_ptr,   g_xh);
    cudaGetSymbolAddress((void**)&outs_ptr, g_outs);
    cudaGetSymbolAddress((void**)&bias_ptr, g_bias);

    // 0) clear flags + fold biases + stage h0 (every launch => replay-safe)
    reset_kernel<<<1, HID>>>(hidden, Wxh_b, Whh_b, bh);

    // 1) xh = input @ Wxh.T + bias        (M=SEQ, N=HID, K=IN)
    {
        dim3 grid(HID / 64, SEQ / 64);
        gemm_nt_bias<<<grid, 256>>>(input, Wxh_w, bias_ptr, xh_ptr,
                                    SEQ, HID, IN_DIM);
    }

    // 2) sequential recurrence (flag-synchronized persistent kernel)
    scan_kernel<<<NB, SCAN_T>>>(Whh_w);

    // 3) logits = outs @ fc_w.T + fc_b    (M=SEQ, N=OUT, K=HID) -> d_out
    {
        dim3 grid(OUT_DIM / 64, SEQ / 64);
        gemm_nt_bias<<<grid, 256>>>(outs_ptr, fc_w, fc_b, out,
                                    SEQ, OUT_DIM, HID);
    }

    // 4) softmax rows in place on d_out
    softmax256<<<SEQ, OUT_DIM>>>(out);
}